// round 1
// baseline (speedup 1.0000x reference)
#include <cuda_runtime.h>
#include <math.h>

#define B_  64
#define U_  256
#define MAT (U_*U_)        // 65536
#define BM_ (B_*MAT)       // 4194304

// ---------------- scratch (allocation-free: __device__ globals) ----------------
__device__ float g_T [BM_];   // reused: T = W^T @ S (or @ sigma_g)
__device__ float g_Sz[BM_];   // Sigma_out_z
__device__ float g_sg[BM_];   // sigma_g
__device__ float g_z [B_*U_];
__device__ float g_gz[B_*U_];
__device__ float g_r [B_*U_];
__device__ float g_gr[B_*U_];
__device__ float g_h [B_*U_];
__device__ float g_gh[B_*U_];
__device__ float g_nx[B_], g_np[B_], g_ngin[B_], g_trS[B_], g_trg[B_];

__device__ __forceinline__ float splus(float x) { return log1pf(expf(x)); }

// ---------------- gates: z, r, h, mu_out, per-batch scalars ----------------
__global__ void gates_kernel(const float* __restrict__ x, const float* __restrict__ prev,
                             const float* __restrict__ S,
                             const float* __restrict__ Uz, const float* __restrict__ Wz,
                             const float* __restrict__ Ur, const float* __restrict__ Wr,
                             const float* __restrict__ Uh, const float* __restrict__ Wh,
                             float* __restrict__ mu_out)
{
    __shared__ float xs[U_], ps[U_], gis[U_], red[U_];
    const int b = blockIdx.x, u = threadIdx.x;
    xs[u] = x[b*U_ + u];
    ps[u] = prev[b*U_ + u];
    __syncthreads();

    float az = 0.f, ar = 0.f;
#pragma unroll 8
    for (int k = 0; k < U_; k++) {
        const float xv = xs[k], pv = ps[k];
        az = fmaf(xv, Uz[k*U_ + u], az);
        az = fmaf(pv, Wz[k*U_ + u], az);
        ar = fmaf(xv, Ur[k*U_ + u], ar);
        ar = fmaf(pv, Wr[k*U_ + u], ar);
    }
    const float z  = 1.f / (1.f + expf(-az));
    const float r  = 1.f / (1.f + expf(-ar));
    const float gz = z * (1.f - z);
    const float gr = r * (1.f - r);
    const float gi = ps[u] * r;
    gis[u] = gi;
    g_z [b*U_+u] = z;  g_gz[b*U_+u] = gz;
    g_r [b*U_+u] = r;  g_gr[b*U_+u] = gr;
    __syncthreads();

    float ah = 0.f;
#pragma unroll 8
    for (int k = 0; k < U_; k++) {
        ah = fmaf(xs[k],  Uh[k*U_ + u], ah);
        ah = fmaf(gis[k], Wh[k*U_ + u], ah);
    }
    const float h  = tanhf(ah);
    const float gh = 1.f - h*h;
    g_h [b*U_+u] = h;  g_gh[b*U_+u] = gh;
    mu_out[b*U_+u] = z * ps[u] + (1.f - z) * h;

    // fixed-order block reductions: ||x||^2, ||prev||^2, ||g_in||^2, tr(S)
    float vals[4] = { xs[u]*xs[u], ps[u]*ps[u], gi*gi, S[b*MAT + u*(U_+1)] };
    float* dst[4] = { g_nx, g_np, g_ngin, g_trS };
    for (int q = 0; q < 4; q++) {
        red[u] = vals[q]; __syncthreads();
        for (int s = 128; s > 0; s >>= 1) { if (u < s) red[u] += red[u+s]; __syncthreads(); }
        if (u == 0) dst[q][b] = red[0];
        __syncthreads();
    }
}

// trace(sigma_g) per batch (deterministic, no atomics)
__global__ void trg_kernel()
{
    __shared__ float red[U_];
    const int b = blockIdx.x, u = threadIdx.x;
    red[u] = g_sg[b*MAT + u*(U_+1)];
    __syncthreads();
    for (int s = 128; s > 0; s >>= 1) { if (u < s) red[u] += red[u+s]; __syncthreads(); }
    if (u == 0) g_trg[b] = red[0];
}

// ---------------- batched GEMM with fused epilogues ----------------
// PH_T : g_T[b] = W^T @ B[b]              (B = Sigma_state, or g_sg if Bsrc==nullptr)
// PH_QZ: Sigma_out_z from g_T[b] @ W_z    (+diag, *outer(gz,gz))
// PH_QR: sigma_g     from g_T[b] @ W_r    (+diag, *outer(gr,gr), hadamard with S)
// PH_QH: final Sigma_out                  (full combination, NaN guard, |diag|)
enum { PH_T = 0, PH_QZ = 1, PH_QR = 2, PH_QH = 3 };

template<int PH>
__global__ void __launch_bounds__(256)
gemm_kernel(const float* __restrict__ Wg,     // shared weight operand
            const float* __restrict__ Bsrc,   // batched source for PH_T (nullptr -> g_sg)
            const float* __restrict__ Sst,
            const float* __restrict__ prev,
            const float* __restrict__ wsig,
            const float* __restrict__ usig,
            float* __restrict__ outp)
{
    __shared__ float As[16][68];   // K-major, padded (272B rows: float4-aligned)
    __shared__ float Bs[16][64];

    const int tx = threadIdx.x, ty = threadIdx.y;
    const int tid = ty*16 + tx;
    const int b  = blockIdx.z;
    const int I0 = blockIdx.y * 64;
    const int J0 = blockIdx.x * 64;

    const float* Bt = Bsrc ? Bsrc : g_sg;

    float acc[4][4];
#pragma unroll
    for (int m = 0; m < 4; m++)
#pragma unroll
        for (int n = 0; n < 4; n++) acc[m][n] = 0.f;

    for (int kt = 0; kt < 16; ++kt) {
        const int k0 = kt * 16;
        if (PH == PH_T) {
#pragma unroll
            for (int t = 0; t < 4; t++) {
                const int idx = tid + t*256;
                const int k = idx >> 6, c = idx & 63;
                As[k][c] = Wg[(k0 + k)*U_ + I0 + c];
                Bs[k][c] = Bt[b*MAT + (k0 + k)*U_ + J0 + c];
            }
        } else {
#pragma unroll
            for (int t = 0; t < 4; t++) {
                const int idx = tid + t*256;
                const int k = idx & 15, c = idx >> 4;
                As[k][c] = g_T[b*MAT + (I0 + c)*U_ + k0 + k];   // transposed load
                const int k2 = idx >> 6, c2 = idx & 63;
                Bs[k2][c2] = Wg[(k0 + k2)*U_ + J0 + c2];
            }
        }
        __syncthreads();
#pragma unroll
        for (int kk = 0; kk < 16; ++kk) {
            const float4 av = *(const float4*)&As[kk][ty*4];
            const float4 bv = *(const float4*)&Bs[kk][tx*4];
            const float a[4]  = { av.x, av.y, av.z, av.w };
            const float bb[4] = { bv.x, bv.y, bv.z, bv.w };
#pragma unroll
            for (int m = 0; m < 4; m++)
#pragma unroll
                for (int n = 0; n < 4; n++)
                    acc[m][n] = fmaf(a[m], bb[n], acc[m][n]);
        }
        __syncthreads();
    }

    const int ib = I0 + ty*4;
    const int jb = J0 + tx*4;

    if (PH == PH_T) {
#pragma unroll
        for (int m = 0; m < 4; m++) {
            float4 v = make_float4(acc[m][0], acc[m][1], acc[m][2], acc[m][3]);
            *(float4*)&g_T[b*MAT + (ib + m)*U_ + jb] = v;
        }
    }
    else if (PH == PH_QZ) {
        const float nx = g_nx[b], np = g_np[b], tr = g_trS[b];
        float gzj[4];
#pragma unroll
        for (int n = 0; n < 4; n++) gzj[n] = g_gz[b*U_ + jb + n];
#pragma unroll
        for (int m = 0; m < 4; m++) {
            const int gi = ib + m;
            const float gzi = g_gz[b*U_ + gi];
            float res[4];
#pragma unroll
            for (int n = 0; n < 4; n++) {
                float q = acc[m][n];
                if (gi == jb + n)
                    q += (np + tr) * splus(wsig[gi]) + nx * splus(usig[gi]);
                res[n] = q * gzi * gzj[n];
            }
            *(float4*)&g_Sz[b*MAT + gi*U_ + jb] = make_float4(res[0], res[1], res[2], res[3]);
        }
    }
    else if (PH == PH_QR) {
        const float nx = g_nx[b], np = g_np[b], tr = g_trS[b];
        float grj[4], rj[4], pj[4];
#pragma unroll
        for (int n = 0; n < 4; n++) {
            const int gj = jb + n;
            grj[n] = g_gr[b*U_ + gj];
            rj[n]  = g_r [b*U_ + gj];
            pj[n]  = prev[b*U_ + gj];
        }
#pragma unroll
        for (int m = 0; m < 4; m++) {
            const int gi = ib + m;
            const float gri = g_gr[b*U_ + gi];
            const float ri  = g_r [b*U_ + gi];
            const float pi  = prev[b*U_ + gi];
            const float4 Sr4 = *(const float4*)&Sst[b*MAT + gi*U_ + jb];
            const float Sv[4] = { Sr4.x, Sr4.y, Sr4.z, Sr4.w };
            float res[4];
#pragma unroll
            for (int n = 0; n < 4; n++) {
                float q = acc[m][n];
                if (gi == jb + n)
                    q += (np + tr) * splus(wsig[gi]) + nx * splus(usig[gi]);
                const float Sig_r = q * gri * grj[n];
                res[n] = Sv[n]*Sig_r + pi*pj[n]*Sig_r + ri*rj[n]*Sv[n];
            }
            *(float4*)&g_sg[b*MAT + gi*U_ + jb] = make_float4(res[0], res[1], res[2], res[3]);
        }
    }
    else { // PH_QH: final combination
        const float nx = g_nx[b], ngin = g_ngin[b], trg = g_trg[b];
        float ghj[4], zj[4], hj[4], pj[4];
#pragma unroll
        for (int n = 0; n < 4; n++) {
            const int gj = jb + n;
            ghj[n] = g_gh[b*U_ + gj];
            zj[n]  = g_z [b*U_ + gj];
            hj[n]  = g_h [b*U_ + gj];
            pj[n]  = prev[b*U_ + gj];
        }
#pragma unroll
        for (int m = 0; m < 4; m++) {
            const int gi = ib + m;
            const float ghi = g_gh[b*U_ + gi];
            const float zi  = g_z [b*U_ + gi];
            const float hi  = g_h [b*U_ + gi];
            const float pi  = prev[b*U_ + gi];
            const float4 Sz4 = *(const float4*)&g_Sz[b*MAT + gi*U_ + jb];
            const float4 Ss4 = *(const float4*)&Sst [b*MAT + gi*U_ + jb];
            const float Szv[4] = { Sz4.x, Sz4.y, Sz4.z, Sz4.w };
            const float Ssv[4] = { Ss4.x, Ss4.y, Ss4.z, Ss4.w };
            float res[4];
#pragma unroll
            for (int n = 0; n < 4; n++) {
                float q = acc[m][n];
                if (gi == jb + n)
                    q += (ngin + trg) * splus(wsig[gi]) + nx * splus(usig[gi]);
                const float Sh = q * ghi * ghj[n];
                const float Sz = Szv[n], Ss = Ssv[n];
                float o = Sz*Ss + zi*zj[n]*Ss + pi*pj[n]*Sz
                        + Sz*Sh + (1.f - zi)*(1.f - zj[n])*Sh + hi*hj[n]*Sz
                        - Sz*(pi*hj[n] + hi*pj[n]);
                const unsigned bits = __float_as_uint(o);
                if (((bits >> 23) & 255u) == 255u) o = 0.f;   // NaN/Inf -> 0
                if (gi == jb + n) o = fabsf(o);               // |diag|
                res[n] = o;
            }
            *(float4*)&outp[b*MAT + gi*U_ + jb] = make_float4(res[0], res[1], res[2], res[3]);
        }
    }
}

// ---------------- launch ----------------
extern "C" void kernel_launch(void* const* d_in, const int* in_sizes, int n_in,
                              void* d_out, int out_size)
{
    const float* x    = (const float*)d_in[0];
    const float* prev = (const float*)d_in[1];
    const float* S    = (const float*)d_in[2];
    const float* Uz   = (const float*)d_in[3];
    const float* uzs  = (const float*)d_in[4];
    const float* Wz   = (const float*)d_in[5];
    const float* wzs  = (const float*)d_in[6];
    const float* Ur   = (const float*)d_in[7];
    const float* urs  = (const float*)d_in[8];
    const float* Wr   = (const float*)d_in[9];
    const float* wrs  = (const float*)d_in[10];
    const float* Uh   = (const float*)d_in[11];
    const float* uhs  = (const float*)d_in[12];
    const float* Wh   = (const float*)d_in[13];
    const float* whs  = (const float*)d_in[14];
    float* out = (float*)d_out;

    gates_kernel<<<B_, U_>>>(x, prev, S, Uz, Wz, Ur, Wr, Uh, Wh, out);

    dim3 blk(16, 16), grd(4, 4, B_);
    // z-gate quad
    gemm_kernel<PH_T ><<<grd, blk>>>(Wz, S,       nullptr, nullptr, nullptr, nullptr, nullptr);
    gemm_kernel<PH_QZ><<<grd, blk>>>(Wz, nullptr, S,       prev,    wzs,     uzs,     nullptr);
    // r-gate quad -> sigma_g
    gemm_kernel<PH_T ><<<grd, blk>>>(Wr, S,       nullptr, nullptr, nullptr, nullptr, nullptr);
    gemm_kernel<PH_QR><<<grd, blk>>>(Wr, nullptr, S,       prev,    wrs,     urs,     nullptr);
    trg_kernel<<<B_, U_>>>();
    // h quad (on sigma_g) -> final Sigma_out
    gemm_kernel<PH_T ><<<grd, blk>>>(Wh, nullptr, nullptr, nullptr, nullptr, nullptr, nullptr);
    gemm_kernel<PH_QH><<<grd, blk>>>(Wh, nullptr, S,       prev,    whs,     uhs,     out + B_*U_);
}

// round 3
// speedup vs baseline: 1.0059x; 1.0059x over previous
#include <cuda_runtime.h>
#include <math.h>

#define B_  64
#define U_  256
#define MAT (U_*U_)        // 65536
#define BM_ (B_*MAT)       // 4194304
#define KT  16
#define TS  128
#define SP  (TS + 4)       // 132 floats/row

// ---------------- scratch (allocation-free __device__ globals; DEVICE-SIDE ACCESS ONLY) ----
__device__ float g_Tz[BM_];   // T for z-gate (K-major/transposed); reused for h-phase
__device__ float g_Tr[BM_];   // T for r-gate (K-major/transposed)
__device__ float g_Sz[BM_];   // Sigma_out_z
__device__ float g_sg[BM_];   // sigma_g
__device__ float g_z [B_*U_];
__device__ float g_gz[B_*U_];
__device__ float g_r [B_*U_];
__device__ float g_gr[B_*U_];
__device__ float g_h [B_*U_];
__device__ float g_gh[B_*U_];
__device__ float g_nx[B_], g_np[B_], g_ngin[B_], g_trS[B_], g_trg[B_];

__device__ __forceinline__ float splus(float x) { return log1pf(expf(x)); }

// ---------------- gates: z, r, h, mu_out, per-batch scalars ----------------
__global__ void gates_kernel(const float* __restrict__ x, const float* __restrict__ prev,
                             const float* __restrict__ S,
                             const float* __restrict__ Uz, const float* __restrict__ Wz,
                             const float* __restrict__ Ur, const float* __restrict__ Wr,
                             const float* __restrict__ Uh, const float* __restrict__ Wh,
                             float* __restrict__ mu_out)
{
    __shared__ float xs[U_], ps[U_], gis[U_], red[U_];
    const int b = blockIdx.x, u = threadIdx.x;
    xs[u] = x[b*U_ + u];
    ps[u] = prev[b*U_ + u];
    __syncthreads();

    float az = 0.f, ar = 0.f;
#pragma unroll 8
    for (int k = 0; k < U_; k++) {
        const float xv = xs[k], pv = ps[k];
        az = fmaf(xv, Uz[k*U_ + u], az);
        az = fmaf(pv, Wz[k*U_ + u], az);
        ar = fmaf(xv, Ur[k*U_ + u], ar);
        ar = fmaf(pv, Wr[k*U_ + u], ar);
    }
    const float z  = 1.f / (1.f + expf(-az));
    const float r  = 1.f / (1.f + expf(-ar));
    const float gz = z * (1.f - z);
    const float gr = r * (1.f - r);
    const float gi = ps[u] * r;
    gis[u] = gi;
    g_z [b*U_+u] = z;  g_gz[b*U_+u] = gz;
    g_r [b*U_+u] = r;  g_gr[b*U_+u] = gr;
    __syncthreads();

    float ah = 0.f;
#pragma unroll 8
    for (int k = 0; k < U_; k++) {
        ah = fmaf(xs[k],  Uh[k*U_ + u], ah);
        ah = fmaf(gis[k], Wh[k*U_ + u], ah);
    }
    const float h  = tanhf(ah);
    const float gh = 1.f - h*h;
    g_h [b*U_+u] = h;  g_gh[b*U_+u] = gh;
    mu_out[b*U_+u] = z * ps[u] + (1.f - z) * h;

    // fixed-order block reductions: ||x||^2, ||prev||^2, ||g_in||^2, tr(S)
    float vals[4] = { xs[u]*xs[u], ps[u]*ps[u], gi*gi, S[b*MAT + u*(U_+1)] };
    float* dst[4] = { g_nx, g_np, g_ngin, g_trS };
    for (int q = 0; q < 4; q++) {
        red[u] = vals[q]; __syncthreads();
        for (int s = 128; s > 0; s >>= 1) { if (u < s) red[u] += red[u+s]; __syncthreads(); }
        if (u == 0) dst[q][b] = red[0];
        __syncthreads();
    }
}

// trace(sigma_g) per batch
__global__ void trg_kernel()
{
    __shared__ float red[U_];
    const int b = blockIdx.x, u = threadIdx.x;
    red[u] = g_sg[b*MAT + u*(U_+1)];
    __syncthreads();
    for (int s = 128; s > 0; s >>= 1) { if (u < s) red[u] += red[u+s]; __syncthreads(); }
    if (u == 0) g_trg[b] = red[0];
}

// ---------------- 128x128x(K=256) GEMM core: 8x8 micro-tile, reg prefetch ----------------
#define GEMM_MAIN(gA, gB)                                                          \
    float acc[8][8];                                                               \
    _Pragma("unroll") for (int m = 0; m < 8; m++)                                  \
    _Pragma("unroll") for (int n = 0; n < 8; n++) acc[m][n] = 0.f;                 \
    {                                                                              \
        const float* pA = (gA) + lr*U_ + lc;                                       \
        const float* pB = (gB) + lr*U_ + lc;                                       \
        float4 a0 = *(const float4*)pA, a1 = *(const float4*)(pA + 4);             \
        float4 b0 = *(const float4*)pB, b1 = *(const float4*)(pB + 4);             \
        for (int kt = 0; kt < U_/KT; ++kt) {                                       \
            __syncthreads();                                                       \
            *(float4*)&As[lr][lc] = a0; *(float4*)&As[lr][lc+4] = a1;              \
            *(float4*)&Bs[lr][lc] = b0; *(float4*)&Bs[lr][lc+4] = b1;              \
            __syncthreads();                                                       \
            if (kt + 1 < U_/KT) {                                                  \
                const float* qA = (gA) + (kt+1)*KT*U_ + lr*U_ + lc;                \
                const float* qB = (gB) + (kt+1)*KT*U_ + lr*U_ + lc;                \
                a0 = *(const float4*)qA; a1 = *(const float4*)(qA + 4);            \
                b0 = *(const float4*)qB; b1 = *(const float4*)(qB + 4);            \
            }                                                                      \
            _Pragma("unroll")                                                      \
            for (int kk = 0; kk < KT; ++kk) {                                      \
                float a[8], bb[8];                                                 \
                *(float4*)&a[0]  = *(const float4*)&As[kk][tr*8];                  \
                *(float4*)&a[4]  = *(const float4*)&As[kk][tr*8 + 4];              \
                *(float4*)&bb[0] = *(const float4*)&Bs[kk][tc*8];                  \
                *(float4*)&bb[4] = *(const float4*)&Bs[kk][tc*8 + 4];              \
                _Pragma("unroll") for (int m = 0; m < 8; m++)                      \
                _Pragma("unroll") for (int n = 0; n < 8; n++)                      \
                    acc[m][n] = fmaf(a[m], bb[n], acc[m][n]);                      \
            }                                                                      \
        }                                                                          \
    }

// T-phase: T = W^T @ src, stored TRANSPOSED/K-major into g_Tz/g_Tr (device symbols only).
// MODE 0: merged z+r, blockIdx.z in [0,128): gate = z>>6 picks (Wz|Wr, g_Tz|g_Tr), src = Sst.
// MODE 1: h-phase, blockIdx.z in [0,64): W = Wa, src = g_sg, out = g_Tz.
template<int MODE>
__global__ void __launch_bounds__(256)
gemmT_kernel(const float* __restrict__ Wa, const float* __restrict__ Wb,
             const float* __restrict__ Sst)
{
    __shared__ float As[KT][SP], Bs[KT][SP];
    const int zz = blockIdx.z;
    const int gate = (MODE == 0) ? (zz >> 6) : 0;
    const int b = zz & 63;
    const float* W = (MODE == 0) ? (gate ? Wb : Wa) : Wa;
    float* outp = ((MODE == 0) ? (gate ? g_Tr : g_Tz) : g_Tz) + b*MAT;
    const float* src = (MODE == 0) ? (Sst + b*MAT) : (g_sg + b*MAT);
    const int I0 = blockIdx.y * TS, J0 = blockIdx.x * TS;
    const int tid = threadIdx.x;
    const int lr = tid >> 4, lc = (tid & 15) << 3;
    const int tr = tid >> 4, tc = tid & 15;

    const float* gA = W + I0;        // A[k][i] = W[k*U + I0+i]
    const float* gB = src + J0;      // B[k][j] = src[k*U + J0+j]

    GEMM_MAIN(gA, gB)

    const int ib = I0 + tr*8, jb = J0 + tc*8;
#pragma unroll
    for (int n = 0; n < 8; n++) {
        *(float4*)&outp[(jb+n)*U_ + ib]     = make_float4(acc[0][n], acc[1][n], acc[2][n], acc[3][n]);
        *(float4*)&outp[(jb+n)*U_ + ib + 4] = make_float4(acc[4][n], acc[5][n], acc[6][n], acc[7][n]);
    }
}

// Q-phase: Q = T @ W with fused epilogues.
// MODE 0: merged QZ(gate0 -> g_Sz) / QR(gate1 -> g_sg), blockIdx.z in [0,128)
// MODE 1: QH final combination -> outp, blockIdx.z in [0,64)
template<int MODE>
__global__ void __launch_bounds__(256)
gemmQ_kernel(const float* __restrict__ Wz_, const float* __restrict__ Wr_,
             const float* __restrict__ Sst, const float* __restrict__ prev,
             const float* __restrict__ ws0, const float* __restrict__ us0,
             const float* __restrict__ ws1, const float* __restrict__ us1,
             float* __restrict__ outp)
{
    __shared__ float As[KT][SP], Bs[KT][SP];
    const int zz = blockIdx.z;
    const int gate = (MODE == 0) ? (zz >> 6) : 0;
    const int b = zz & 63;
    const int I0 = blockIdx.y * TS, J0 = blockIdx.x * TS;
    const int tid = threadIdx.x;
    const int lr = tid >> 4, lc = (tid & 15) << 3;
    const int tr = tid >> 4, tc = tid & 15;

    const float* Tsrc = (MODE == 0) ? (gate ? g_Tr : g_Tz) : g_Tz;
    const float* W    = (MODE == 0) ? (gate ? Wr_  : Wz_ ) : Wz_;
    const float* gA = Tsrc + b*MAT + I0;      // Tt[k*U + i] = T[i,k]
    const float* gB = W + J0;

    GEMM_MAIN(gA, gB)

    const int ib = I0 + tr*8, jb = J0 + tc*8;
    const float* wsig = gate ? ws1 : ws0;
    const float* usig = gate ? us1 : us0;

    if (MODE == 0 && gate == 0) {             // ---- QZ: Sigma_out_z ----
        const float nx = g_nx[b], sc = g_np[b] + g_trS[b];
        float gzj[8];
#pragma unroll
        for (int n = 0; n < 8; n++) gzj[n] = g_gz[b*U_ + jb + n];
#pragma unroll
        for (int m = 0; m < 8; m++) {
            const int gi = ib + m;
            const float gzi = g_gz[b*U_ + gi];
            float res[8];
#pragma unroll
            for (int n = 0; n < 8; n++) {
                float q = acc[m][n];
                if (gi == jb + n) q += sc * splus(wsig[gi]) + nx * splus(usig[gi]);
                res[n] = q * gzi * gzj[n];
            }
            *(float4*)&g_Sz[b*MAT + gi*U_ + jb]     = *(float4*)&res[0];
            *(float4*)&g_Sz[b*MAT + gi*U_ + jb + 4] = *(float4*)&res[4];
        }
    }
    else if (MODE == 0) {                      // ---- QR: sigma_g ----
        const float nx = g_nx[b], sc = g_np[b] + g_trS[b];
        float grj[8], rj[8], pj[8];
#pragma unroll
        for (int n = 0; n < 8; n++) {
            const int gj = jb + n;
            grj[n] = g_gr[b*U_ + gj];
            rj[n]  = g_r [b*U_ + gj];
            pj[n]  = prev[b*U_ + gj];
        }
#pragma unroll
        for (int m = 0; m < 8; m++) {
            const int gi = ib + m;
            const float gri = g_gr[b*U_ + gi];
            const float ri  = g_r [b*U_ + gi];
            const float pi  = prev[b*U_ + gi];
            float Sv[8];
            *(float4*)&Sv[0] = *(const float4*)&Sst[b*MAT + gi*U_ + jb];
            *(float4*)&Sv[4] = *(const float4*)&Sst[b*MAT + gi*U_ + jb + 4];
            float res[8];
#pragma unroll
            for (int n = 0; n < 8; n++) {
                float q = acc[m][n];
                if (gi == jb + n) q += sc * splus(wsig[gi]) + nx * splus(usig[gi]);
                const float Sig_r = q * gri * grj[n];
                res[n] = Sv[n]*Sig_r + pi*pj[n]*Sig_r + ri*rj[n]*Sv[n];
            }
            *(float4*)&g_sg[b*MAT + gi*U_ + jb]     = *(float4*)&res[0];
            *(float4*)&g_sg[b*MAT + gi*U_ + jb + 4] = *(float4*)&res[4];
        }
    }
    else {                                     // ---- QH: final Sigma_out ----
        const float nx = g_nx[b], sc = g_ngin[b] + g_trg[b];
        float ghj[8], zj[8], hj[8], pj[8];
#pragma unroll
        for (int n = 0; n < 8; n++) {
            const int gj = jb + n;
            ghj[n] = g_gh[b*U_ + gj];
            zj[n]  = g_z [b*U_ + gj];
            hj[n]  = g_h [b*U_ + gj];
            pj[n]  = prev[b*U_ + gj];
        }
#pragma unroll
        for (int m = 0; m < 8; m++) {
            const int gi = ib + m;
            const float ghi = g_gh[b*U_ + gi];
            const float zi  = g_z [b*U_ + gi];
            const float hi  = g_h [b*U_ + gi];
            const float pi  = prev[b*U_ + gi];
            float Szv[8], Ssv[8];
            *(float4*)&Szv[0] = *(const float4*)&g_Sz[b*MAT + gi*U_ + jb];
            *(float4*)&Szv[4] = *(const float4*)&g_Sz[b*MAT + gi*U_ + jb + 4];
            *(float4*)&Ssv[0] = *(const float4*)&Sst [b*MAT + gi*U_ + jb];
            *(float4*)&Ssv[4] = *(const float4*)&Sst [b*MAT + gi*U_ + jb + 4];
            float res[8];
#pragma unroll
            for (int n = 0; n < 8; n++) {
                float q = acc[m][n];
                if (gi == jb + n) q += sc * splus(wsig[gi]) + nx * splus(usig[gi]);
                const float Sh = q * ghi * ghj[n];
                const float Sz = Szv[n], Ss = Ssv[n];
                float o = Sz*Ss + zi*zj[n]*Ss + pi*pj[n]*Sz
                        + Sz*Sh + (1.f - zi)*(1.f - zj[n])*Sh + hi*hj[n]*Sz
                        - Sz*(pi*hj[n] + hi*pj[n]);
                const unsigned bits = __float_as_uint(o);
                if (((bits >> 23) & 255u) == 255u) o = 0.f;   // NaN/Inf -> 0
                if (gi == jb + n) o = fabsf(o);               // |diag|
                res[n] = o;
            }
            *(float4*)&outp[b*MAT + gi*U_ + jb]     = *(float4*)&res[0];
            *(float4*)&outp[b*MAT + gi*U_ + jb + 4] = *(float4*)&res[4];
        }
    }
}

// ---------------- launch (only harness pointers cross the host/device boundary) ----------
extern "C" void kernel_launch(void* const* d_in, const int* in_sizes, int n_in,
                              void* d_out, int out_size)
{
    const float* x    = (const float*)d_in[0];
    const float* prev = (const float*)d_in[1];
    const float* S    = (const float*)d_in[2];
    const float* Uz   = (const float*)d_in[3];
    const float* uzs  = (const float*)d_in[4];
    const float* Wz   = (const float*)d_in[5];
    const float* wzs  = (const float*)d_in[6];
    const float* Ur   = (const float*)d_in[7];
    const float* urs  = (const float*)d_in[8];
    const float* Wr   = (const float*)d_in[9];
    const float* wrs  = (const float*)d_in[10];
    const float* Uh   = (const float*)d_in[11];
    const float* uhs  = (const float*)d_in[12];
    const float* Wh   = (const float*)d_in[13];
    const float* whs  = (const float*)d_in[14];
    float* out = (float*)d_out;

    gates_kernel<<<B_, U_>>>(x, prev, S, Uz, Wz, Ur, Wr, Uh, Wh, out);

    dim3 blk(256), grd2(2, 2, 128), grd1(2, 2, 64);
    // z+r T-phases (merged): g_Tz = (Wz^T S)^T, g_Tr = (Wr^T S)^T
    gemmT_kernel<0><<<grd2, blk>>>(Wz, Wr, S);
    // z+r Q-phases (merged): Sigma_out_z and sigma_g
    gemmQ_kernel<0><<<grd2, blk>>>(Wz, Wr, S, prev, wzs, uzs, wrs, urs, out + B_*U_);
    trg_kernel<<<B_, U_>>>();
    // h T-phase on sigma_g (-> g_Tz), then final combination
    gemmT_kernel<1><<<grd1, blk>>>(Wh, Wh, S);
    gemmQ_kernel<1><<<grd1, blk>>>(Wh, Wh, S, prev, whs, uhs, whs, uhs, out + B_*U_);
}

// round 5
// speedup vs baseline: 1.4971x; 1.4883x over previous
#include <cuda_runtime.h>
#include <cuda_bf16.h>
#include <math.h>
#include <stdint.h>

#define B_  64
#define U_  256
#define MAT (U_*U_)
#define BM_ (B_*MAT)
#define SPAD 264          // bf16 per smem row (528B: 16B-aligned, conflict-free ldmatrix)

// ---------------- scratch (__device__ globals; device-side access only) ----------------
__device__ __align__(16) __nv_bfloat16 g_Sb [BM_];   // S in bf16
__device__ __align__(16) __nv_bfloat16 g_Wtz[MAT];   // W^T bf16 per gate
__device__ __align__(16) __nv_bfloat16 g_Wtr[MAT];
__device__ __align__(16) __nv_bfloat16 g_Wth[MAT];
__device__ __align__(16) __nv_bfloat16 g_Tzb[BM_];   // T = W^T S (bf16); reused for h
__device__ __align__(16) __nv_bfloat16 g_Trb[BM_];
__device__ __align__(16) __nv_bfloat16 g_sgb[BM_];   // sigma_g bf16
__device__ __align__(16) float g_Sz[BM_];            // Sigma_out_z fp32
__device__ float g_dg[B_*U_];                        // fp32 diag of sigma_g
__device__ float g_z [B_*U_], g_gz[B_*U_], g_r [B_*U_], g_gr[B_*U_];
__device__ float g_h [B_*U_], g_gh[B_*U_];
__device__ float g_nx[B_], g_np[B_], g_ngin[B_], g_trS[B_], g_trg[B_];

__device__ __forceinline__ float splus(float x) { return log1pf(expf(x)); }

__device__ __forceinline__ uint32_t smem_u32(const void* p) {
    uint32_t a;
    asm("{ .reg .u64 t; cvta.to.shared.u64 t, %1; cvt.u32.u64 %0, t; }" : "=r"(a) : "l"(p));
    return a;
}
__device__ __forceinline__ uint32_t pack_bf2(float lo, float hi) {
    __nv_bfloat162 v = __floats2bfloat162_rn(lo, hi);
    return *(uint32_t*)&v;
}
__device__ __forceinline__ void ldsm_x4(uint32_t* r, uint32_t addr) {
    asm volatile("ldmatrix.sync.aligned.m8n8.x4.shared.b16 {%0,%1,%2,%3}, [%4];"
        : "=r"(r[0]), "=r"(r[1]), "=r"(r[2]), "=r"(r[3]) : "r"(addr));
}
__device__ __forceinline__ void ldsm_x2(uint32_t* r, uint32_t addr) {
    asm volatile("ldmatrix.sync.aligned.m8n8.x2.shared.b16 {%0,%1}, [%2];"
        : "=r"(r[0]), "=r"(r[1]) : "r"(addr));
}
__device__ __forceinline__ void mma16816(float* c, const uint32_t* a, const uint32_t* b) {
    asm volatile("mma.sync.aligned.m16n8k16.row.col.f32.bf16.bf16.f32 "
        "{%0,%1,%2,%3}, {%4,%5,%6,%7}, {%8,%9}, {%0,%1,%2,%3};"
        : "+f"(c[0]), "+f"(c[1]), "+f"(c[2]), "+f"(c[3])
        : "r"(a[0]), "r"(a[1]), "r"(a[2]), "r"(a[3]), "r"(b[0]), "r"(b[1]));
}

// ---------------- gates (fp32-exact) ----------------
__global__ void gates_kernel(const float* __restrict__ x, const float* __restrict__ prev,
                             const float* __restrict__ S,
                             const float* __restrict__ Uz, const float* __restrict__ Wz,
                             const float* __restrict__ Ur, const float* __restrict__ Wr,
                             const float* __restrict__ Uh, const float* __restrict__ Wh,
                             float* __restrict__ mu_out)
{
    __shared__ float xs[U_], ps[U_], gis[U_], red[U_];
    const int b = blockIdx.x, u = threadIdx.x;
    xs[u] = x[b*U_ + u];
    ps[u] = prev[b*U_ + u];
    __syncthreads();

    float az = 0.f, ar = 0.f;
#pragma unroll 8
    for (int k = 0; k < U_; k++) {
        const float xv = xs[k], pv = ps[k];
        az = fmaf(xv, Uz[k*U_ + u], az);
        az = fmaf(pv, Wz[k*U_ + u], az);
        ar = fmaf(xv, Ur[k*U_ + u], ar);
        ar = fmaf(pv, Wr[k*U_ + u], ar);
    }
    const float z  = 1.f / (1.f + expf(-az));
    const float r  = 1.f / (1.f + expf(-ar));
    const float gi = ps[u] * r;
    gis[u] = gi;
    g_z [b*U_+u] = z;  g_gz[b*U_+u] = z * (1.f - z);
    g_r [b*U_+u] = r;  g_gr[b*U_+u] = r * (1.f - r);
    __syncthreads();

    float ah = 0.f;
#pragma unroll 8
    for (int k = 0; k < U_; k++) {
        ah = fmaf(xs[k],  Uh[k*U_ + u], ah);
        ah = fmaf(gis[k], Wh[k*U_ + u], ah);
    }
    const float h = tanhf(ah);
    g_h [b*U_+u] = h;  g_gh[b*U_+u] = 1.f - h*h;
    mu_out[b*U_+u] = z * ps[u] + (1.f - z) * h;

    float vals[4] = { xs[u]*xs[u], ps[u]*ps[u], gi*gi, S[b*MAT + u*(U_+1)] };
    float* dst[4] = { g_nx, g_np, g_ngin, g_trS };
    for (int q = 0; q < 4; q++) {
        red[u] = vals[q]; __syncthreads();
        for (int s = 128; s > 0; s >>= 1) { if (u < s) red[u] += red[u+s]; __syncthreads(); }
        if (u == 0) dst[q][b] = red[0];
        __syncthreads();
    }
}

__global__ void trg_kernel()
{
    __shared__ float red[U_];
    const int b = blockIdx.x, u = threadIdx.x;
    red[u] = g_dg[b*U_ + u];
    __syncthreads();
    for (int s = 128; s > 0; s >>= 1) { if (u < s) red[u] += red[u+s]; __syncthreads(); }
    if (u == 0) g_trg[b] = red[0];
}

// ---------------- prep: S -> bf16 ----------------
__global__ void convS_kernel(const float* __restrict__ S)
{
    const int base = (blockIdx.x * 256 + threadIdx.x) * 8;
    float4 f0 = *(const float4*)(S + base);
    float4 f1 = *(const float4*)(S + base + 4);
    uint4 o;
    o.x = pack_bf2(f0.x, f0.y); o.y = pack_bf2(f0.z, f0.w);
    o.z = pack_bf2(f1.x, f1.y); o.w = pack_bf2(f1.z, f1.w);
    *(uint4*)(g_Sb + base) = o;
}

// ---------------- prep: W^T -> bf16 (3 gates) ----------------
__global__ void transW_kernel(const float* __restrict__ Wz, const float* __restrict__ Wr,
                              const float* __restrict__ Wh)
{
    __shared__ float tile[32][33];
    const float* W = (blockIdx.z == 0) ? Wz : (blockIdx.z == 1) ? Wr : Wh;
    __nv_bfloat16* Wt = (blockIdx.z == 0) ? g_Wtz : (blockIdx.z == 1) ? g_Wtr : g_Wth;
    const int m0 = blockIdx.y * 32, i0 = blockIdx.x * 32;
    const int tx = threadIdx.x, ty = threadIdx.y;
    tile[ty][tx] = W[(m0 + ty) * U_ + i0 + tx];
    __syncthreads();
    Wt[(i0 + ty) * U_ + m0 + tx] = __float2bfloat16_rn(tile[tx][ty]);
}

// ---------------- HMMA phases ----------------
// All GEMMs are D[i,j] = sum_k A[i,k]*B[j,k]  (K-major operands, S/sigma_g symmetric)
// PH 0: T_{z,r} = Wt_g . S           -> g_Tzb/g_Trb (bf16)           grid (4,64,2)
// PH 1: Q_{z,r} = T_g . Wt_g^T(rows) -> Sigma_z fp32 / sigma_g bf16  grid (4,64,2)
// PH 2: T_h = Wt_h . sigma_g         -> g_Tzb (bf16)                 grid (4,64,1)
// PH 3: Q_h  = T_h . (rows of Wt_h)  -> final Sigma_out fp32         grid (4,64,1)
#define SM_DYN (2 * 128 * SPAD * 2)

template<int PH>
__global__ void __launch_bounds__(256)
mma_phase(const float* __restrict__ Sst, const float* __restrict__ prev,
          const float* __restrict__ ws0, const float* __restrict__ us0,
          const float* __restrict__ ws1, const float* __restrict__ us1,
          float* __restrict__ outp)
{
    extern __shared__ __nv_bfloat16 sm[];
    __nv_bfloat16* smA = sm;
    __nv_bfloat16* smB = sm + 128 * SPAD;

    const int tid = threadIdx.x, lane = tid & 31, wid = tid >> 5;
    const int mt = blockIdx.x >> 1, nt = blockIdx.x & 1;
    const int b = blockIdx.y, gate = blockIdx.z;
    const int i0 = mt * 128, j0 = nt * 128;

    const __nv_bfloat16 *Asrc, *Bsrc;
    if (PH == 0)      { Asrc = (gate ? g_Wtr : g_Wtz) + i0*U_;         Bsrc = g_Sb  + b*MAT + j0*U_; }
    else if (PH == 1) { Asrc = (gate ? g_Trb : g_Tzb) + b*MAT + i0*U_; Bsrc = (gate ? g_Wtr : g_Wtz) + j0*U_; }
    else if (PH == 2) { Asrc = g_Wth + i0*U_;                          Bsrc = g_sgb + b*MAT + j0*U_; }
    else              { Asrc = g_Tzb + b*MAT + i0*U_;                  Bsrc = g_Wth + j0*U_; }

    for (int t = tid; t < 4096; t += 256) {
        const int r = t >> 5, c = (t & 31) << 3;
        *(uint4*)(smA + r*SPAD + c) = *(const uint4*)(Asrc + r*U_ + c);
        *(uint4*)(smB + r*SPAD + c) = *(const uint4*)(Bsrc + r*U_ + c);
    }
    __syncthreads();

    const int warp_m = wid & 3, warp_n = wid >> 2;   // warp tile: 32 x 64
    float acc[2][8][4];
#pragma unroll
    for (int ms = 0; ms < 2; ms++)
#pragma unroll
        for (int ns = 0; ns < 8; ns++)
#pragma unroll
            for (int q = 0; q < 4; q++) acc[ms][ns][q] = 0.f;

    const uint32_t baseA = smem_u32(smA), baseB = smem_u32(smB);
    const int arow = (lane & 7) | (((lane >> 3) & 1) << 3);
    const int akof = (lane >> 4) << 3;
    const int brow = lane & 7;
    const int bkof = ((lane >> 3) & 1) << 3;

#pragma unroll 2
    for (int ks = 0; ks < 16; ks++) {
        const int k0 = ks * 16;
        uint32_t af[2][4];
#pragma unroll
        for (int ms = 0; ms < 2; ms++)
            ldsm_x4(af[ms], baseA + (uint32_t)(((warp_m*32 + ms*16 + arow)*SPAD + k0 + akof) * 2));
        uint32_t bf[8][2];
#pragma unroll
        for (int ns = 0; ns < 8; ns++)
            ldsm_x2(bf[ns], baseB + (uint32_t)(((warp_n*64 + ns*8 + brow)*SPAD + k0 + bkof) * 2));
#pragma unroll
        for (int ms = 0; ms < 2; ms++)
#pragma unroll
            for (int ns = 0; ns < 8; ns++)
                mma16816(acc[ms][ns], af[ms], bf[ns]);
    }

    // ---- fused epilogues on HMMA fragment layout ----
    const int rb = lane >> 2;            // 0..7
    const int cb = (lane & 3) << 1;      // 0,2,4,6

#pragma unroll
    for (int ms = 0; ms < 2; ms++) {
#pragma unroll
        for (int hh = 0; hh < 2; hh++) {
            const int row = i0 + warp_m*32 + ms*16 + hh*8 + rb;

            if (PH == 0 || PH == 2) {
                __nv_bfloat16* Tb = (((PH == 0) ? (gate ? g_Trb : g_Tzb) : g_Tzb)) + b*MAT + row*U_;
#pragma unroll
                for (int ns = 0; ns < 8; ns++) {
                    const int colg = j0 + warp_n*64 + ns*8 + cb;
                    *(uint32_t*)(Tb + colg) = pack_bf2(acc[ms][ns][hh*2], acc[ms][ns][hh*2 + 1]);
                }
            }
            else if (PH == 1 && gate == 0) {           // Sigma_out_z (fp32)
                const float nx = g_nx[b], sc = g_np[b] + g_trS[b];
                const float dadd = sc * splus(ws0[row]) + nx * splus(us0[row]);
                const float gzi = g_gz[b*U_ + row];
                float* dstr = g_Sz + b*MAT + row*U_;
#pragma unroll
                for (int ns = 0; ns < 8; ns++) {
                    const int colg = j0 + warp_n*64 + ns*8 + cb;
                    float v0 = acc[ms][ns][hh*2], v1 = acc[ms][ns][hh*2 + 1];
                    if (colg == row)     v0 += dadd;
                    if (colg + 1 == row) v1 += dadd;
                    float2 o;
                    o.x = v0 * gzi * g_gz[b*U_ + colg];
                    o.y = v1 * gzi * g_gz[b*U_ + colg + 1];
                    *(float2*)(dstr + colg) = o;
                }
            }
            else if (PH == 1) {                        // sigma_g (bf16 + fp32 diag)
                const float nx = g_nx[b], sc = g_np[b] + g_trS[b];
                const float dadd = sc * splus(ws1[row]) + nx * splus(us1[row]);
                const float gri = g_gr[b*U_ + row];
                const float ri  = g_r [b*U_ + row];
                const float pi  = prev[b*U_ + row];
                const float* Srow = Sst + b*MAT + row*U_;
                __nv_bfloat16* dstr = g_sgb + b*MAT + row*U_;
#pragma unroll
                for (int ns = 0; ns < 8; ns++) {
                    const int colg = j0 + warp_n*64 + ns*8 + cb;
                    float v0 = acc[ms][ns][hh*2], v1 = acc[ms][ns][hh*2 + 1];
                    if (colg == row)     v0 += dadd;
                    if (colg + 1 == row) v1 += dadd;
                    const float2 Sv = *(const float2*)(Srow + colg);
                    const float sr0 = v0 * gri * g_gr[b*U_ + colg];
                    const float sr1 = v1 * gri * g_gr[b*U_ + colg + 1];
                    const float res0 = Sv.x*sr0 + pi*prev[b*U_ + colg]*sr0     + ri*g_r[b*U_ + colg]*Sv.x;
                    const float res1 = Sv.y*sr1 + pi*prev[b*U_ + colg + 1]*sr1 + ri*g_r[b*U_ + colg + 1]*Sv.y;
                    if (colg == row)     g_dg[b*U_ + row] = res0;
                    if (colg + 1 == row) g_dg[b*U_ + row] = res1;
                    *(uint32_t*)(dstr + colg) = pack_bf2(res0, res1);
                }
            }
            else {                                     // PH 3: final Sigma_out
                const float nx = g_nx[b], sc = g_ngin[b] + g_trg[b];
                const float dadd = sc * splus(ws0[row]) + nx * splus(us0[row]);
                const float ghi = g_gh[b*U_ + row];
                const float zi  = g_z [b*U_ + row];
                const float hi  = g_h [b*U_ + row];
                const float pi  = prev[b*U_ + row];
                const float* Szrow = g_Sz + b*MAT + row*U_;
                const float* Srow  = Sst  + b*MAT + row*U_;
                float* dstr = outp + b*MAT + row*U_;
#pragma unroll
                for (int ns = 0; ns < 8; ns++) {
                    const int colg = j0 + warp_n*64 + ns*8 + cb;
                    float v0 = acc[ms][ns][hh*2], v1 = acc[ms][ns][hh*2 + 1];
                    if (colg == row)     v0 += dadd;
                    if (colg + 1 == row) v1 += dadd;
                    float2 o;
#pragma unroll
                    for (int e = 0; e < 2; e++) {
                        const int j = colg + e;
                        const float q = (e == 0) ? v0 : v1;
                        const float Sh = q * ghi * g_gh[b*U_ + j];
                        const float Sz = Szrow[j], Ss = Srow[j];
                        const float zj = g_z[b*U_ + j], hj = g_h[b*U_ + j], pj = prev[b*U_ + j];
                        float oo = Sz*Ss + zi*zj*Ss + pi*pj*Sz
                                 + Sz*Sh + (1.f - zi)*(1.f - zj)*Sh + hi*hj*Sz
                                 - Sz*(pi*hj + hi*pj);
                        const unsigned bits = __float_as_uint(oo);
                        if (((bits >> 23) & 255u) == 255u) oo = 0.f;
                        if (j == row) oo = fabsf(oo);
                        (e == 0 ? o.x : o.y) = oo;
                    }
                    *(float2*)(dstr + colg) = o;
                }
            }
        }
    }
}

// ---------------- launch ----------------
extern "C" void kernel_launch(void* const* d_in, const int* in_sizes, int n_in,
                              void* d_out, int out_size)
{
    const float* x    = (const float*)d_in[0];
    const float* prev = (const float*)d_in[1];
    const float* S    = (const float*)d_in[2];
    const float* Uz   = (const float*)d_in[3];
    const float* uzs  = (const float*)d_in[4];
    const float* Wz   = (const float*)d_in[5];
    const float* wzs  = (const float*)d_in[6];
    const float* Ur   = (const float*)d_in[7];
    const float* urs  = (const float*)d_in[8];
    const float* Wr   = (const float*)d_in[9];
    const float* wrs  = (const float*)d_in[10];
    const float* Uh   = (const float*)d_in[11];
    const float* uhs  = (const float*)d_in[12];
    const float* Wh   = (const float*)d_in[13];
    const float* whs  = (const float*)d_in[14];
    float* out = (float*)d_out;

    cudaFuncSetAttribute(mma_phase<0>, cudaFuncAttributeMaxDynamicSharedMemorySize, SM_DYN);
    cudaFuncSetAttribute(mma_phase<1>, cudaFuncAttributeMaxDynamicSharedMemorySize, SM_DYN);
    cudaFuncSetAttribute(mma_phase<2>, cudaFuncAttributeMaxDynamicSharedMemorySize, SM_DYN);
    cudaFuncSetAttribute(mma_phase<3>, cudaFuncAttributeMaxDynamicSharedMemorySize, SM_DYN);

    convS_kernel<<<2048, 256>>>(S);
    transW_kernel<<<dim3(8, 8, 3), dim3(32, 32)>>>(Wz, Wr, Wh);
    gates_kernel<<<B_, U_>>>(x, prev, S, Uz, Wz, Ur, Wr, Uh, Wh, out);

    float* sig_out = out + B_*U_;
    mma_phase<0><<<dim3(4, 64, 2), 256, SM_DYN>>>(S, prev, wzs, uzs, wrs, urs, sig_out);
    mma_phase<1><<<dim3(4, 64, 2), 256, SM_DYN>>>(S, prev, wzs, uzs, wrs, urs, sig_out);
    trg_kernel<<<B_, U_>>>();
    mma_phase<2><<<dim3(4, 64, 1), 256, SM_DYN>>>(S, prev, whs, uhs, whs, uhs, sig_out);
    mma_phase<3><<<dim3(4, 64, 1), 256, SM_DYN>>>(S, prev, whs, uhs, whs, uhs, sig_out);
}

// round 6
// speedup vs baseline: 2.3021x; 1.5377x over previous
#include <cuda_runtime.h>
#include <cuda_bf16.h>
#include <math.h>
#include <stdint.h>

#define B_  64
#define U_  256
#define MAT (U_*U_)
#define BM_ (B_*MAT)
#define KC   64           // K-chunk
#define NCH  (U_/KC)      // 4 chunks
#define SPAD 72           // bf16 per smem row (144B; +4 words mod 32 per row -> ldmatrix conflict-free)
#define TILE_E (128*SPAD) // elems per tile
#define SM_DYN (4*TILE_E*2)  // 2 buffers x (A+B) x 128 x 72 x 2B = 73728

// ---------------- scratch (__device__ globals; device-side access only) ----------------
__device__ __align__(16) __nv_bfloat16 g_Sb [BM_];
__device__ __align__(16) __nv_bfloat16 g_Wtz[MAT];
__device__ __align__(16) __nv_bfloat16 g_Wtr[MAT];
__device__ __align__(16) __nv_bfloat16 g_Wth[MAT];
__device__ __align__(16) __nv_bfloat16 g_Tzb[BM_];
__device__ __align__(16) __nv_bfloat16 g_Trb[BM_];
__device__ __align__(16) __nv_bfloat16 g_sgb[BM_];
__device__ __align__(16) float g_Sz[BM_];
__device__ float g_dg[B_*U_];
__device__ float g_z [B_*U_], g_gz[B_*U_], g_r [B_*U_], g_gr[B_*U_];
__device__ float g_h [B_*U_], g_gh[B_*U_];
__device__ float g_nx[B_], g_np[B_], g_ngin[B_], g_trS[B_], g_trg[B_];

__device__ __forceinline__ float splus(float x) { return log1pf(expf(x)); }

__device__ __forceinline__ uint32_t smem_u32(const void* p) {
    uint32_t a;
    asm("{ .reg .u64 t; cvta.to.shared.u64 t, %1; cvt.u32.u64 %0, t; }" : "=r"(a) : "l"(p));
    return a;
}
__device__ __forceinline__ uint32_t pack_bf2(float lo, float hi) {
    __nv_bfloat162 v = __floats2bfloat162_rn(lo, hi);
    return *(uint32_t*)&v;
}
__device__ __forceinline__ void ldsm_x4(uint32_t* r, uint32_t addr) {
    asm volatile("ldmatrix.sync.aligned.m8n8.x4.shared.b16 {%0,%1,%2,%3}, [%4];"
        : "=r"(r[0]), "=r"(r[1]), "=r"(r[2]), "=r"(r[3]) : "r"(addr));
}
__device__ __forceinline__ void ldsm_x2(uint32_t* r, uint32_t addr) {
    asm volatile("ldmatrix.sync.aligned.m8n8.x2.shared.b16 {%0,%1}, [%2];"
        : "=r"(r[0]), "=r"(r[1]) : "r"(addr));
}
__device__ __forceinline__ void mma16816(float* c, const uint32_t* a, const uint32_t* b) {
    asm volatile("mma.sync.aligned.m16n8k16.row.col.f32.bf16.bf16.f32 "
        "{%0,%1,%2,%3}, {%4,%5,%6,%7}, {%8,%9}, {%0,%1,%2,%3};"
        : "+f"(c[0]), "+f"(c[1]), "+f"(c[2]), "+f"(c[3])
        : "r"(a[0]), "r"(a[1]), "r"(a[2]), "r"(a[3]), "r"(b[0]), "r"(b[1]));
}
__device__ __forceinline__ void cpa16(uint32_t dst, const void* src) {
    asm volatile("cp.async.cg.shared.global [%0], [%1], 16;" :: "r"(dst), "l"(src));
}
#define CPA_COMMIT() asm volatile("cp.async.commit_group;" ::: "memory")
#define CPA_WAIT1()  asm volatile("cp.async.wait_group 1;" ::: "memory")
#define CPA_WAIT0()  asm volatile("cp.async.wait_group 0;" ::: "memory")

// ---------------- gates (fp32-exact) ----------------
__global__ void gates_kernel(const float* __restrict__ x, const float* __restrict__ prev,
                             const float* __restrict__ S,
                             const float* __restrict__ Uz, const float* __restrict__ Wz,
                             const float* __restrict__ Ur, const float* __restrict__ Wr,
                             const float* __restrict__ Uh, const float* __restrict__ Wh,
                             float* __restrict__ mu_out)
{
    __shared__ float xs[U_], ps[U_], gis[U_], red[U_];
    const int b = blockIdx.x, u = threadIdx.x;
    xs[u] = x[b*U_ + u];
    ps[u] = prev[b*U_ + u];
    __syncthreads();

    float az = 0.f, ar = 0.f;
#pragma unroll 8
    for (int k = 0; k < U_; k++) {
        const float xv = xs[k], pv = ps[k];
        az = fmaf(xv, Uz[k*U_ + u], az);
        az = fmaf(pv, Wz[k*U_ + u], az);
        ar = fmaf(xv, Ur[k*U_ + u], ar);
        ar = fmaf(pv, Wr[k*U_ + u], ar);
    }
    const float z  = 1.f / (1.f + expf(-az));
    const float r  = 1.f / (1.f + expf(-ar));
    const float gi = ps[u] * r;
    gis[u] = gi;
    g_z [b*U_+u] = z;  g_gz[b*U_+u] = z * (1.f - z);
    g_r [b*U_+u] = r;  g_gr[b*U_+u] = r * (1.f - r);
    __syncthreads();

    float ah = 0.f;
#pragma unroll 8
    for (int k = 0; k < U_; k++) {
        ah = fmaf(xs[k],  Uh[k*U_ + u], ah);
        ah = fmaf(gis[k], Wh[k*U_ + u], ah);
    }
    const float h = tanhf(ah);
    g_h [b*U_+u] = h;  g_gh[b*U_+u] = 1.f - h*h;
    mu_out[b*U_+u] = z * ps[u] + (1.f - z) * h;

    float vals[4] = { xs[u]*xs[u], ps[u]*ps[u], gi*gi, S[b*MAT + u*(U_+1)] };
    float* dst[4] = { g_nx, g_np, g_ngin, g_trS };
    for (int q = 0; q < 4; q++) {
        red[u] = vals[q]; __syncthreads();
        for (int s = 128; s > 0; s >>= 1) { if (u < s) red[u] += red[u+s]; __syncthreads(); }
        if (u == 0) dst[q][b] = red[0];
        __syncthreads();
    }
}

__global__ void trg_kernel()
{
    __shared__ float red[U_];
    const int b = blockIdx.x, u = threadIdx.x;
    red[u] = g_dg[b*U_ + u];
    __syncthreads();
    for (int s = 128; s > 0; s >>= 1) { if (u < s) red[u] += red[u+s]; __syncthreads(); }
    if (u == 0) g_trg[b] = red[0];
}

// ---------------- prep: S -> bf16 ----------------
__global__ void convS_kernel(const float* __restrict__ S)
{
    const int base = (blockIdx.x * 256 + threadIdx.x) * 8;
    float4 f0 = *(const float4*)(S + base);
    float4 f1 = *(const float4*)(S + base + 4);
    uint4 o;
    o.x = pack_bf2(f0.x, f0.y); o.y = pack_bf2(f0.z, f0.w);
    o.z = pack_bf2(f1.x, f1.y); o.w = pack_bf2(f1.z, f1.w);
    *(uint4*)(g_Sb + base) = o;
}

// ---------------- prep: W^T -> bf16 (3 gates) ----------------
__global__ void transW_kernel(const float* __restrict__ Wz, const float* __restrict__ Wr,
                              const float* __restrict__ Wh)
{
    __shared__ float tile[32][33];
    const float* W = (blockIdx.z == 0) ? Wz : (blockIdx.z == 1) ? Wr : Wh;
    __nv_bfloat16* Wt = (blockIdx.z == 0) ? g_Wtz : (blockIdx.z == 1) ? g_Wtr : g_Wth;
    const int m0 = blockIdx.y * 32, i0 = blockIdx.x * 32;
    const int tx = threadIdx.x, ty = threadIdx.y;
    tile[ty][tx] = W[(m0 + ty) * U_ + i0 + tx];
    __syncthreads();
    Wt[(i0 + ty) * U_ + m0 + tx] = __float2bfloat16_rn(tile[tx][ty]);
}

// ---------------- HMMA phases: cp.async double-buffered K pipeline ----------------
// D[i,j] = sum_k A[i,k]*B[j,k]  (K-major operands; S/sigma_g symmetric)
template<int PH>
__global__ void __launch_bounds__(256, 2)
mma_phase(const float* __restrict__ Sst, const float* __restrict__ prev,
          const float* __restrict__ ws0, const float* __restrict__ us0,
          const float* __restrict__ ws1, const float* __restrict__ us1,
          float* __restrict__ outp)
{
    extern __shared__ __nv_bfloat16 sm[];

    const int tid = threadIdx.x, lane = tid & 31, wid = tid >> 5;
    const int mt = blockIdx.x >> 1, nt = blockIdx.x & 1;
    const int b = blockIdx.y, gate = blockIdx.z;
    const int i0 = mt * 128, j0 = nt * 128;

    const __nv_bfloat16 *Asrc, *Bsrc;
    if (PH == 0)      { Asrc = (gate ? g_Wtr : g_Wtz) + i0*U_;         Bsrc = g_Sb  + b*MAT + j0*U_; }
    else if (PH == 1) { Asrc = (gate ? g_Trb : g_Tzb) + b*MAT + i0*U_; Bsrc = (gate ? g_Wtr : g_Wtz) + j0*U_; }
    else if (PH == 2) { Asrc = g_Wth + i0*U_;                          Bsrc = g_sgb + b*MAT + j0*U_; }
    else              { Asrc = g_Tzb + b*MAT + i0*U_;                  Bsrc = g_Wth + j0*U_; }

    const uint32_t smb = smem_u32(sm);
    // per-thread load coords: 4 x 16B per tile per chunk
    const int lr0 = tid >> 3;              // +32 per step
    const int lc0 = (tid & 7) << 3;

    // issue chunk loads into buffer `buf`
    auto load_chunk = [&](int buf, int ch) {
        const uint32_t dA = smb + (uint32_t)((buf*2*TILE_E) * 2);
        const uint32_t dB = smb + (uint32_t)((buf*2*TILE_E + TILE_E) * 2);
        const int kb = ch * KC;
#pragma unroll
        for (int i = 0; i < 4; i++) {
            const int r = lr0 + i*32;
            cpa16(dA + (uint32_t)((r*SPAD + lc0) * 2), Asrc + r*U_ + kb + lc0);
            cpa16(dB + (uint32_t)((r*SPAD + lc0) * 2), Bsrc + r*U_ + kb + lc0);
        }
        CPA_COMMIT();
    };

    load_chunk(0, 0);
    load_chunk(1, 1);

    const int warp_m = wid & 3, warp_n = wid >> 2;   // warp tile: 32 x 64
    float acc[2][8][4];
#pragma unroll
    for (int ms = 0; ms < 2; ms++)
#pragma unroll
        for (int ns = 0; ns < 8; ns++)
#pragma unroll
            for (int q = 0; q < 4; q++) acc[ms][ns][q] = 0.f;

    const int arow = (lane & 7) | (((lane >> 3) & 1) << 3);
    const int akof = (lane >> 4) << 3;
    const int brow = lane & 7;
    const int bkof = ((lane >> 3) & 1) << 3;

    for (int ch = 0; ch < NCH; ch++) {
        if (ch < NCH - 1) { CPA_WAIT1(); } else { CPA_WAIT0(); }
        __syncthreads();
        const int buf = ch & 1;
        const uint32_t baseA = smb + (uint32_t)((buf*2*TILE_E) * 2);
        const uint32_t baseB = smb + (uint32_t)((buf*2*TILE_E + TILE_E) * 2);
#pragma unroll
        for (int ks = 0; ks < KC/16; ks++) {
            const int k0 = ks * 16;
            uint32_t af[2][4];
#pragma unroll
            for (int ms = 0; ms < 2; ms++)
                ldsm_x4(af[ms], baseA + (uint32_t)(((warp_m*32 + ms*16 + arow)*SPAD + k0 + akof) * 2));
            uint32_t bf[8][2];
#pragma unroll
            for (int ns = 0; ns < 8; ns++)
                ldsm_x2(bf[ns], baseB + (uint32_t)(((warp_n*64 + ns*8 + brow)*SPAD + k0 + bkof) * 2));
#pragma unroll
            for (int ms = 0; ms < 2; ms++)
#pragma unroll
                for (int ns = 0; ns < 8; ns++)
                    mma16816(acc[ms][ns], af[ms], bf[ns]);
        }
        __syncthreads();
        if (ch + 2 < NCH) load_chunk(buf, ch + 2);
    }

    // ---- fused epilogues on HMMA fragment layout ----
    const int rb = lane >> 2;            // 0..7
    const int cb = (lane & 3) << 1;      // 0,2,4,6

#pragma unroll
    for (int ms = 0; ms < 2; ms++) {
#pragma unroll
        for (int hh = 0; hh < 2; hh++) {
            const int row = i0 + warp_m*32 + ms*16 + hh*8 + rb;

            if (PH == 0 || PH == 2) {
                __nv_bfloat16* Tb = (((PH == 0) ? (gate ? g_Trb : g_Tzb) : g_Tzb)) + b*MAT + row*U_;
#pragma unroll
                for (int ns = 0; ns < 8; ns++) {
                    const int colg = j0 + warp_n*64 + ns*8 + cb;
                    *(uint32_t*)(Tb + colg) = pack_bf2(acc[ms][ns][hh*2], acc[ms][ns][hh*2 + 1]);
                }
            }
            else if (PH == 1 && gate == 0) {           // Sigma_out_z (fp32)
                const float nx = g_nx[b], sc = g_np[b] + g_trS[b];
                const float dadd = sc * splus(ws0[row]) + nx * splus(us0[row]);
                const float gzi = g_gz[b*U_ + row];
                float* dstr = g_Sz + b*MAT + row*U_;
#pragma unroll
                for (int ns = 0; ns < 8; ns++) {
                    const int colg = j0 + warp_n*64 + ns*8 + cb;
                    float v0 = acc[ms][ns][hh*2], v1 = acc[ms][ns][hh*2 + 1];
                    if (colg == row)     v0 += dadd;
                    if (colg + 1 == row) v1 += dadd;
                    float2 o;
                    o.x = v0 * gzi * g_gz[b*U_ + colg];
                    o.y = v1 * gzi * g_gz[b*U_ + colg + 1];
                    *(float2*)(dstr + colg) = o;
                }
            }
            else if (PH == 1) {                        // sigma_g (bf16 + fp32 diag)
                const float nx = g_nx[b], sc = g_np[b] + g_trS[b];
                const float dadd = sc * splus(ws1[row]) + nx * splus(us1[row]);
                const float gri = g_gr[b*U_ + row];
                const float ri  = g_r [b*U_ + row];
                const float pi  = prev[b*U_ + row];
                const float* Srow = Sst + b*MAT + row*U_;
                __nv_bfloat16* dstr = g_sgb + b*MAT + row*U_;
#pragma unroll
                for (int ns = 0; ns < 8; ns++) {
                    const int colg = j0 + warp_n*64 + ns*8 + cb;
                    float v0 = acc[ms][ns][hh*2], v1 = acc[ms][ns][hh*2 + 1];
                    if (colg == row)     v0 += dadd;
                    if (colg + 1 == row) v1 += dadd;
                    const float2 Sv = *(const float2*)(Srow + colg);
                    const float sr0 = v0 * gri * g_gr[b*U_ + colg];
                    const float sr1 = v1 * gri * g_gr[b*U_ + colg + 1];
                    const float res0 = Sv.x*sr0 + pi*prev[b*U_ + colg]*sr0     + ri*g_r[b*U_ + colg]*Sv.x;
                    const float res1 = Sv.y*sr1 + pi*prev[b*U_ + colg + 1]*sr1 + ri*g_r[b*U_ + colg + 1]*Sv.y;
                    if (colg == row)     g_dg[b*U_ + row] = res0;
                    if (colg + 1 == row) g_dg[b*U_ + row] = res1;
                    *(uint32_t*)(dstr + colg) = pack_bf2(res0, res1);
                }
            }
            else {                                     // PH 3: final Sigma_out
                const float nx = g_nx[b], sc = g_ngin[b] + g_trg[b];
                const float dadd = sc * splus(ws0[row]) + nx * splus(us0[row]);
                const float ghi = g_gh[b*U_ + row];
                const float zi  = g_z [b*U_ + row];
                const float hi  = g_h [b*U_ + row];
                const float pi  = prev[b*U_ + row];
                const float* Szrow = g_Sz + b*MAT + row*U_;
                const float* Srow  = Sst  + b*MAT + row*U_;
                float* dstr = outp + b*MAT + row*U_;
#pragma unroll
                for (int ns = 0; ns < 8; ns++) {
                    const int colg = j0 + warp_n*64 + ns*8 + cb;
                    float v0 = acc[ms][ns][hh*2], v1 = acc[ms][ns][hh*2 + 1];
                    if (colg == row)     v0 += dadd;
                    if (colg + 1 == row) v1 += dadd;
                    float2 o;
#pragma unroll
                    for (int e = 0; e < 2; e++) {
                        const int j = colg + e;
                        const float q = (e == 0) ? v0 : v1;
                        const float Sh = q * ghi * g_gh[b*U_ + j];
                        const float Sz = Szrow[j], Ss = Srow[j];
                        const float zj = g_z[b*U_ + j], hj = g_h[b*U_ + j], pj = prev[b*U_ + j];
                        float oo = Sz*Ss + zi*zj*Ss + pi*pj*Sz
                                 + Sz*Sh + (1.f - zi)*(1.f - zj)*Sh + hi*hj*Sz
                                 - Sz*(pi*hj + hi*pj);
                        const unsigned bits = __float_as_uint(oo);
                        if (((bits >> 23) & 255u) == 255u) oo = 0.f;
                        if (j == row) oo = fabsf(oo);
                        (e == 0 ? o.x : o.y) = oo;
                    }
                    *(float2*)(dstr + colg) = o;
                }
            }
        }
    }
}

// ---------------- launch ----------------
extern "C" void kernel_launch(void* const* d_in, const int* in_sizes, int n_in,
                              void* d_out, int out_size)
{
    const float* x    = (const float*)d_in[0];
    const float* prev = (const float*)d_in[1];
    const float* S    = (const float*)d_in[2];
    const float* Uz   = (const float*)d_in[3];
    const float* uzs  = (const float*)d_in[4];
    const float* Wz   = (const float*)d_in[5];
    const float* wzs  = (const float*)d_in[6];
    const float* Ur   = (const float*)d_in[7];
    const float* urs  = (const float*)d_in[8];
    const float* Wr   = (const float*)d_in[9];
    const float* wrs  = (const float*)d_in[10];
    const float* Uh   = (const float*)d_in[11];
    const float* uhs  = (const float*)d_in[12];
    const float* Wh   = (const float*)d_in[13];
    const float* whs  = (const float*)d_in[14];
    float* out = (float*)d_out;

    cudaFuncSetAttribute(mma_phase<0>, cudaFuncAttributeMaxDynamicSharedMemorySize, SM_DYN);
    cudaFuncSetAttribute(mma_phase<1>, cudaFuncAttributeMaxDynamicSharedMemorySize, SM_DYN);
    cudaFuncSetAttribute(mma_phase<2>, cudaFuncAttributeMaxDynamicSharedMemorySize, SM_DYN);
    cudaFuncSetAttribute(mma_phase<3>, cudaFuncAttributeMaxDynamicSharedMemorySize, SM_DYN);

    convS_kernel<<<2048, 256>>>(S);
    transW_kernel<<<dim3(8, 8, 3), dim3(32, 32)>>>(Wz, Wr, Wh);
    gates_kernel<<<B_, U_>>>(x, prev, S, Uz, Wz, Ur, Wr, Uh, Wh, out);

    float* sig_out = out + B_*U_;
    mma_phase<0><<<dim3(4, 64, 2), 256, SM_DYN>>>(S, prev, wzs, uzs, wrs, urs, sig_out);
    mma_phase<1><<<dim3(4, 64, 2), 256, SM_DYN>>>(S, prev, wzs, uzs, wrs, urs, sig_out);
    trg_kernel<<<B_, U_>>>();
    mma_phase<2><<<dim3(4, 64, 1), 256, SM_DYN>>>(S, prev, whs, uhs, whs, uhs, sig_out);
    mma_phase<3><<<dim3(4, 64, 1), 256, SM_DYN>>>(S, prev, whs, uhs, whs, uhs, sig_out);
}